// round 7
// baseline (speedup 1.0000x reference)
#include <cuda_runtime.h>

#define EPS 1e-6f
#define D_DIM 128
#define MAX_I 16384
#define MAX_JK 8192

// ---- scratch (no allocations allowed) ----
__device__ float  g_col_rl[MAX_I];
__device__ float  g_col_ul[MAX_I];
__device__ float  g_cL[MAX_I];      // |l_i|^2 - 2*eps*sum(l_i)
__device__ float  g_normR[MAX_JK];  // |r_j + eps|^2
__device__ float  g_normU[MAX_JK];  // |u_k + eps|^2
__device__ double g_edge;

__device__ __forceinline__ float fsqrt_approx(float x) {
    float r; asm("sqrt.approx.f32 %0, %1;" : "=f"(r) : "f"(x)); return r;
}
// packed fp32x2 FMA (Blackwell): c.lo += a.lo*b.lo ; c.hi += a.hi*b.hi
__device__ __forceinline__ void ffma2(unsigned long long &c,
                                      unsigned long long a,
                                      unsigned long long b) {
    asm("fma.rn.f32x2 %0, %1, %2, %0;" : "+l"(c) : "l"(a), "l"(b));
}

// ---------------------------------------------------------------- init
__global__ void init_kernel(int I) {
    int t = blockIdx.x * blockDim.x + threadIdx.x;
    if (t < I) { g_col_rl[t] = 0.f; g_col_ul[t] = 0.f; }
    if (t == 0) g_edge = 0.0;
}

// ------------------------------------------------------------- norms
// one warp per row; D=128 -> one float4 per lane
__global__ void norms_kernel(const float* __restrict__ L,
                             const float* __restrict__ R,
                             const float* __restrict__ U,
                             int I, int J, int K) {
    int warp = (blockIdx.x * blockDim.x + threadIdx.x) >> 5;
    int lane = threadIdx.x & 31;
    int rows = I + J + K;
    if (warp >= rows) return;

    const float* src; int mode, rowid;
    if (warp < J)          { src = R + (size_t)warp * D_DIM;          mode = 0; rowid = warp; }
    else if (warp < J + K) { src = U + (size_t)(warp - J) * D_DIM;    mode = 1; rowid = warp - J; }
    else                   { src = L + (size_t)(warp - J - K) * D_DIM; mode = 2; rowid = warp - J - K; }

    float4 v = ((const float4*)src)[lane];
    if (mode < 2) { v.x += EPS; v.y += EPS; v.z += EPS; v.w += EPS; }
    float s2 = v.x * v.x + v.y * v.y + v.z * v.z + v.w * v.w;
    float s1 = v.x + v.y + v.z + v.w;
    #pragma unroll
    for (int off = 16; off; off >>= 1) {
        s2 += __shfl_down_sync(0xffffffffu, s2, off);
        s1 += __shfl_down_sync(0xffffffffu, s1, off);
    }
    if (lane == 0) {
        if (mode == 0)      g_normR[rowid] = s2;
        else if (mode == 1) g_normU[rowid] = s2;
        else                g_cL[rowid]    = s2 - 2.0f * EPS * s1;
    }
}

// ----------------------------------------------------- fused exp-GEMM
// col[i] += sum_j exp(bias[j] - (sqrt(max(normA[j]+cL[i]-2*A_j.B_i,0)) + eps))
// Block tile: 128 (j) x 64 (i), 256 threads, per-thread 8x4, k paired in f32x2.
#define BJ 128
#define BI 64
#define BK 16
#define PITCH 18   // even (8B-aligned k-pairs), tx*18 mod 32 hits 16 distinct banks

__global__ __launch_bounds__(256, 2)
void exp_gemm_kernel(const float* __restrict__ A,   // [J, D]
                     const float* __restrict__ Bm,  // [I, D] (latent_l)
                     const float* __restrict__ bias,
                     int which)                     // 0: rl, 1: ul
{
    __shared__ float As[BJ * PITCH];
    __shared__ float Bs[BI * PITCH];
    __shared__ float cs[16][BI];

    const float* normA = which ? g_normU : g_normR;
    float* col         = which ? g_col_ul : g_col_rl;

    const int tid = threadIdx.x;
    const int tx = tid & 15, ty = tid >> 4;
    const int j0 = blockIdx.y * BJ;
    const int i0 = blockIdx.x * BI;

    unsigned long long acc[8][4];
    #pragma unroll
    for (int m = 0; m < 8; m++)
        #pragma unroll
        for (int n = 0; n < 4; n++) acc[m][n] = 0ull;

    for (int kk = 0; kk < D_DIM; kk += BK) {
        // stage A: 128 rows x 16 k = 512 float4 over 256 threads
        #pragma unroll
        for (int r2 = 0; r2 < 2; r2++) {
            int idx = tid + r2 * 256;
            int row = idx >> 2, c = idx & 3;
            float4 v = *(const float4*)(A + (size_t)(j0 + row) * D_DIM + kk + c * 4);
            float* s = &As[row * PITCH + c * 4];
            s[0] = v.x; s[1] = v.y; s[2] = v.z; s[3] = v.w;
        }
        // stage B: 64 rows x 16 k = 256 float4
        {
            int row = tid >> 2, c = tid & 3;
            float4 v = *(const float4*)(Bm + (size_t)(i0 + row) * D_DIM + kk + c * 4);
            float* s = &Bs[row * PITCH + c * 4];
            s[0] = v.x; s[1] = v.y; s[2] = v.z; s[3] = v.w;
        }
        __syncthreads();

        #pragma unroll
        for (int kp = 0; kp < 8; kp++) {
            unsigned long long a2[8], b2[4];
            #pragma unroll
            for (int m = 0; m < 8; m++)
                a2[m] = *(const unsigned long long*)&As[(ty + 16 * m) * PITCH + kp * 2];
            #pragma unroll
            for (int n = 0; n < 4; n++)
                b2[n] = *(const unsigned long long*)&Bs[(tx + 16 * n) * PITCH + kp * 2];
            #pragma unroll
            for (int m = 0; m < 8; m++)
                #pragma unroll
                for (int n = 0; n < 4; n++)
                    ffma2(acc[m][n], a2[m], b2[n]);
        }
        __syncthreads();
    }

    // epilogue: fold k-pair halves, distance -> exp -> column sums over j
    float na[8], ba[8];
    #pragma unroll
    for (int m = 0; m < 8; m++) {
        int j = j0 + ty + 16 * m;
        na[m] = normA[j];
        ba[m] = bias[j];
    }
    #pragma unroll
    for (int n = 0; n < 4; n++) {
        int il = tx + 16 * n;
        float cb = g_cL[i0 + il];
        float csum = 0.f;
        #pragma unroll
        for (int m = 0; m < 8; m++) {
            float lo, hi;
            asm("mov.b64 {%0,%1}, %2;" : "=f"(lo), "=f"(hi) : "l"(acc[m][n]));
            float dot = lo + hi;
            float d2  = na[m] + cb - 2.f * dot;
            float d   = fsqrt_approx(fmaxf(d2, 0.f)) + EPS;
            csum += __expf(ba[m] - d);
        }
        cs[ty][il] = csum;
    }
    __syncthreads();
    if (tid < BI) {
        float s = 0.f;
        #pragma unroll
        for (int t2 = 0; t2 < 16; t2++) s += cs[t2][tid];
        atomicAdd(&col[i0 + tid], s);
    }
}

// -------------------------------------------------------------- edges
// 8 lanes per edge, grid-stride; coalesced float4 row gathers (L2-resident tables)
__global__ void edge_kernel(const float* __restrict__ L, const float* __restrict__ R,
                            const float* __restrict__ U,
                            const float* __restrict__ rho, const float* __restrict__ nu,
                            const float* __restrict__ tau,
                            const float* __restrict__ w,
                            const int* __restrict__ si, const int* __restrict__ sj,
                            const int* __restrict__ sk, int E)
{
    const int lane8 = threadIdx.x & 7;
    int grp  = (blockIdx.x * blockDim.x + threadIdx.x) >> 3;
    int ngrp = (gridDim.x * blockDim.x) >> 3;

    float local = 0.f;
    for (int e = grp; e < E; e += ngrp) {
        int ii = si[e], jj = sj[e], kk = sk[e];
        const float4* lp = (const float4*)(L + (size_t)ii * D_DIM);
        const float4* rp = (const float4*)(R + (size_t)jj * D_DIM);
        const float4* up = (const float4*)(U + (size_t)kk * D_DIM);
        float slr = 0.f, slu = 0.f;
        #pragma unroll
        for (int q = 0; q < 4; q++) {
            float4 lv = lp[q * 8 + lane8];
            float4 rv = rp[q * 8 + lane8];
            float4 uv = up[q * 8 + lane8];
            float d0 = lv.x - rv.x + EPS, d1 = lv.y - rv.y + EPS;
            float d2 = lv.z - rv.z + EPS, d3 = lv.w - rv.w + EPS;
            slr += d0 * d0 + d1 * d1 + d2 * d2 + d3 * d3;
            d0 = lv.x - uv.x + EPS; d1 = lv.y - uv.y + EPS;
            d2 = lv.z - uv.z + EPS; d3 = lv.w - uv.w + EPS;
            slu += d0 * d0 + d1 * d1 + d2 * d2 + d3 * d3;
        }
        #pragma unroll
        for (int off = 4; off; off >>= 1) {
            slr += __shfl_down_sync(0xffffffffu, slr, off, 8);
            slu += __shfl_down_sync(0xffffffffu, slu, off, 8);
        }
        if (lane8 == 0) {
            float bias = rho[ii] + nu[jj] + tau[kk];
            local += w[e] * (bias - fsqrt_approx(slr) - fsqrt_approx(slu));
        }
    }

    __shared__ float red[256];
    red[threadIdx.x] = local;
    __syncthreads();
    #pragma unroll
    for (int s = 128; s; s >>= 1) {
        if ((int)threadIdx.x < s) red[threadIdx.x] += red[threadIdx.x + s];
        __syncthreads();
    }
    if (threadIdx.x == 0) atomicAdd(&g_edge, (double)red[0]);
}

// -------------------------------------------------------------- final
__global__ void final_kernel(const float* __restrict__ rho, int I, float* __restrict__ out) {
    __shared__ double sd[256];
    double z1 = 0.0;
    for (int i = threadIdx.x; i < I; i += blockDim.x)
        z1 += (double)g_col_rl[i] * (double)g_col_ul[i] * (double)__expf(rho[i]);
    sd[threadIdx.x] = z1;
    __syncthreads();
    #pragma unroll
    for (int s = 128; s; s >>= 1) {
        if ((int)threadIdx.x < s) sd[threadIdx.x] += sd[threadIdx.x + s];
        __syncthreads();
    }
    if (threadIdx.x == 0) out[0] = (float)(g_edge - sd[0]);
}

// -------------------------------------------------------------- launch
extern "C" void kernel_launch(void* const* d_in, const int* in_sizes, int n_in,
                              void* d_out, int out_size) {
    const float* L   = (const float*)d_in[0];
    const float* R   = (const float*)d_in[1];
    const float* U   = (const float*)d_in[2];
    const float* rho = (const float*)d_in[3];
    const float* nu  = (const float*)d_in[4];
    const float* tau = (const float*)d_in[5];
    const float* w   = (const float*)d_in[6];
    const int* si = (const int*)d_in[7];
    const int* sj = (const int*)d_in[8];
    const int* sk = (const int*)d_in[9];

    int I = in_sizes[3];  // rho
    int J = in_sizes[4];  // nu
    int K = in_sizes[5];  // tau
    int E = in_sizes[6];  // sample_weights

    init_kernel<<<(I + 255) / 256, 256>>>(I);

    int rows = I + J + K;
    norms_kernel<<<(rows * 32 + 255) / 256, 256>>>(L, R, U, I, J, K);

    dim3 g_rl(I / BI, J / BJ);
    exp_gemm_kernel<<<g_rl, 256>>>(R, L, nu, 0);
    dim3 g_ul(I / BI, K / BJ);
    exp_gemm_kernel<<<g_ul, 256>>>(U, L, tau, 1);

    edge_kernel<<<1184, 256>>>(L, R, U, rho, nu, tau, w, si, sj, sk, E);

    final_kernel<<<1, 256>>>(rho, I, (float*)d_out);
}

// round 8
// speedup vs baseline: 1.0013x; 1.0013x over previous
#include <cuda_runtime.h>

#define EPS 1e-6f
#define D_DIM 128
#define MAX_I 16384
#define MAX_JK 8192

// ---- scratch (no allocations allowed) ----
__device__ float  g_col_rl[MAX_I];
__device__ float  g_col_ul[MAX_I];
__device__ float  g_cL[MAX_I];      // |l_i|^2 - 2*eps*sum(l_i)
__device__ float  g_normR[MAX_JK];  // |r_j + eps|^2
__device__ float  g_normU[MAX_JK];  // |u_k + eps|^2
__device__ double g_edge;

__device__ __forceinline__ float fsqrt_approx(float x) {
    float r; asm("sqrt.approx.f32 %0, %1;" : "=f"(r) : "f"(x)); return r;
}
// packed fp32x2 FMA (Blackwell): c.lo += a.lo*b.lo ; c.hi += a.hi*b.hi
__device__ __forceinline__ void ffma2(unsigned long long &c,
                                      unsigned long long a,
                                      unsigned long long b) {
    asm("fma.rn.f32x2 %0, %1, %2, %0;" : "+l"(c) : "l"(a), "l"(b));
}

// ---------------------------------------------------------------- init
__global__ void init_kernel(int I) {
    int t = blockIdx.x * blockDim.x + threadIdx.x;
    if (t < I) { g_col_rl[t] = 0.f; g_col_ul[t] = 0.f; }
    if (t == 0) g_edge = 0.0;
}

// ------------------------------------------------------------- norms
// one warp per row; D=128 -> one float4 per lane
__global__ void norms_kernel(const float* __restrict__ L,
                             const float* __restrict__ R,
                             const float* __restrict__ U,
                             int I, int J, int K) {
    int warp = (blockIdx.x * blockDim.x + threadIdx.x) >> 5;
    int lane = threadIdx.x & 31;
    int rows = I + J + K;
    if (warp >= rows) return;

    const float* src; int mode, rowid;
    if (warp < J)          { src = R + (size_t)warp * D_DIM;          mode = 0; rowid = warp; }
    else if (warp < J + K) { src = U + (size_t)(warp - J) * D_DIM;    mode = 1; rowid = warp - J; }
    else                   { src = L + (size_t)(warp - J - K) * D_DIM; mode = 2; rowid = warp - J - K; }

    float4 v = ((const float4*)src)[lane];
    if (mode < 2) { v.x += EPS; v.y += EPS; v.z += EPS; v.w += EPS; }
    float s2 = v.x * v.x + v.y * v.y + v.z * v.z + v.w * v.w;
    float s1 = v.x + v.y + v.z + v.w;
    #pragma unroll
    for (int off = 16; off; off >>= 1) {
        s2 += __shfl_down_sync(0xffffffffu, s2, off);
        s1 += __shfl_down_sync(0xffffffffu, s1, off);
    }
    if (lane == 0) {
        if (mode == 0)      g_normR[rowid] = s2;
        else if (mode == 1) g_normU[rowid] = s2;
        else                g_cL[rowid]    = s2 - 2.0f * EPS * s1;
    }
}

// ----------------------------------------------------- fused exp-GEMM
// col[i] += sum_j exp(bias[j] - (sqrt(max(normA[j]+cL[i]-2*A_j.B_i,0)) + eps))
// Block tile: 128 (j) x 64 (i), 256 threads, per-thread 8x4, k paired in f32x2.
#define BJ 128
#define BI 64
#define BK 16
#define PITCH 18   // even (8B-aligned k-pairs), tx*18 mod 32 hits 16 distinct banks

__global__ __launch_bounds__(256, 2)
void exp_gemm_kernel(const float* __restrict__ A,   // [J, D]
                     const float* __restrict__ Bm,  // [I, D] (latent_l)
                     const float* __restrict__ bias,
                     int which)                     // 0: rl, 1: ul
{
    __shared__ float As[BJ * PITCH];
    __shared__ float Bs[BI * PITCH];
    __shared__ float cs[16][BI];

    const float* normA = which ? g_normU : g_normR;
    float* col         = which ? g_col_ul : g_col_rl;

    const int tid = threadIdx.x;
    const int tx = tid & 15, ty = tid >> 4;
    const int j0 = blockIdx.y * BJ;
    const int i0 = blockIdx.x * BI;

    unsigned long long acc[8][4];
    #pragma unroll
    for (int m = 0; m < 8; m++)
        #pragma unroll
        for (int n = 0; n < 4; n++) acc[m][n] = 0ull;

    for (int kk = 0; kk < D_DIM; kk += BK) {
        // stage A: 128 rows x 16 k = 512 float4 over 256 threads
        #pragma unroll
        for (int r2 = 0; r2 < 2; r2++) {
            int idx = tid + r2 * 256;
            int row = idx >> 2, c = idx & 3;
            float4 v = *(const float4*)(A + (size_t)(j0 + row) * D_DIM + kk + c * 4);
            float* s = &As[row * PITCH + c * 4];
            s[0] = v.x; s[1] = v.y; s[2] = v.z; s[3] = v.w;
        }
        // stage B: 64 rows x 16 k = 256 float4
        {
            int row = tid >> 2, c = tid & 3;
            float4 v = *(const float4*)(Bm + (size_t)(i0 + row) * D_DIM + kk + c * 4);
            float* s = &Bs[row * PITCH + c * 4];
            s[0] = v.x; s[1] = v.y; s[2] = v.z; s[3] = v.w;
        }
        __syncthreads();

        #pragma unroll
        for (int kp = 0; kp < 8; kp++) {
            unsigned long long a2[8], b2[4];
            #pragma unroll
            for (int m = 0; m < 8; m++)
                a2[m] = *(const unsigned long long*)&As[(ty + 16 * m) * PITCH + kp * 2];
            #pragma unroll
            for (int n = 0; n < 4; n++)
                b2[n] = *(const unsigned long long*)&Bs[(tx + 16 * n) * PITCH + kp * 2];
            #pragma unroll
            for (int m = 0; m < 8; m++)
                #pragma unroll
                for (int n = 0; n < 4; n++)
                    ffma2(acc[m][n], a2[m], b2[n]);
        }
        __syncthreads();
    }

    // epilogue: fold k-pair halves, distance -> exp -> column sums over j
    float na[8], ba[8];
    #pragma unroll
    for (int m = 0; m < 8; m++) {
        int j = j0 + ty + 16 * m;
        na[m] = normA[j];
        ba[m] = bias[j];
    }
    #pragma unroll
    for (int n = 0; n < 4; n++) {
        int il = tx + 16 * n;
        float cb = g_cL[i0 + il];
        float csum = 0.f;
        #pragma unroll
        for (int m = 0; m < 8; m++) {
            float lo, hi;
            asm("mov.b64 {%0,%1}, %2;" : "=f"(lo), "=f"(hi) : "l"(acc[m][n]));
            float dot = lo + hi;
            float d2  = na[m] + cb - 2.f * dot;
            float d   = fsqrt_approx(fmaxf(d2, 0.f)) + EPS;
            csum += __expf(ba[m] - d);
        }
        cs[ty][il] = csum;
    }
    __syncthreads();
    if (tid < BI) {
        float s = 0.f;
        #pragma unroll
        for (int t2 = 0; t2 < 16; t2++) s += cs[t2][tid];
        atomicAdd(&col[i0 + tid], s);
    }
}

// -------------------------------------------------------------- edges
// 8 lanes per edge, grid-stride; coalesced float4 row gathers (L2-resident tables)
__global__ void edge_kernel(const float* __restrict__ L, const float* __restrict__ R,
                            const float* __restrict__ U,
                            const float* __restrict__ rho, const float* __restrict__ nu,
                            const float* __restrict__ tau,
                            const float* __restrict__ w,
                            const int* __restrict__ si, const int* __restrict__ sj,
                            const int* __restrict__ sk, int E)
{
    const int lane8 = threadIdx.x & 7;
    int grp  = (blockIdx.x * blockDim.x + threadIdx.x) >> 3;
    int ngrp = (gridDim.x * blockDim.x) >> 3;

    float local = 0.f;
    for (int e = grp; e < E; e += ngrp) {
        int ii = si[e], jj = sj[e], kk = sk[e];
        const float4* lp = (const float4*)(L + (size_t)ii * D_DIM);
        const float4* rp = (const float4*)(R + (size_t)jj * D_DIM);
        const float4* up = (const float4*)(U + (size_t)kk * D_DIM);
        float slr = 0.f, slu = 0.f;
        #pragma unroll
        for (int q = 0; q < 4; q++) {
            float4 lv = lp[q * 8 + lane8];
            float4 rv = rp[q * 8 + lane8];
            float4 uv = up[q * 8 + lane8];
            float d0 = lv.x - rv.x + EPS, d1 = lv.y - rv.y + EPS;
            float d2 = lv.z - rv.z + EPS, d3 = lv.w - rv.w + EPS;
            slr += d0 * d0 + d1 * d1 + d2 * d2 + d3 * d3;
            d0 = lv.x - uv.x + EPS; d1 = lv.y - uv.y + EPS;
            d2 = lv.z - uv.z + EPS; d3 = lv.w - uv.w + EPS;
            slu += d0 * d0 + d1 * d1 + d2 * d2 + d3 * d3;
        }
        #pragma unroll
        for (int off = 4; off; off >>= 1) {
            slr += __shfl_down_sync(0xffffffffu, slr, off, 8);
            slu += __shfl_down_sync(0xffffffffu, slu, off, 8);
        }
        if (lane8 == 0) {
            float bias = rho[ii] + nu[jj] + tau[kk];
            local += w[e] * (bias - fsqrt_approx(slr) - fsqrt_approx(slu));
        }
    }

    __shared__ float red[256];
    red[threadIdx.x] = local;
    __syncthreads();
    #pragma unroll
    for (int s = 128; s; s >>= 1) {
        if ((int)threadIdx.x < s) red[threadIdx.x] += red[threadIdx.x + s];
        __syncthreads();
    }
    if (threadIdx.x == 0) atomicAdd(&g_edge, (double)red[0]);
}

// -------------------------------------------------------------- final
__global__ void final_kernel(const float* __restrict__ rho, int I, float* __restrict__ out) {
    __shared__ double sd[256];
    double z1 = 0.0;
    for (int i = threadIdx.x; i < I; i += blockDim.x)
        z1 += (double)g_col_rl[i] * (double)g_col_ul[i] * (double)__expf(rho[i]);
    sd[threadIdx.x] = z1;
    __syncthreads();
    #pragma unroll
    for (int s = 128; s; s >>= 1) {
        if ((int)threadIdx.x < s) sd[threadIdx.x] += sd[threadIdx.x + s];
        __syncthreads();
    }
    if (threadIdx.x == 0) out[0] = (float)(g_edge - sd[0]);
}

// -------------------------------------------------------------- launch
extern "C" void kernel_launch(void* const* d_in, const int* in_sizes, int n_in,
                              void* d_out, int out_size) {
    const float* L   = (const float*)d_in[0];
    const float* R   = (const float*)d_in[1];
    const float* U   = (const float*)d_in[2];
    const float* rho = (const float*)d_in[3];
    const float* nu  = (const float*)d_in[4];
    const float* tau = (const float*)d_in[5];
    const float* w   = (const float*)d_in[6];
    const int* si = (const int*)d_in[7];
    const int* sj = (const int*)d_in[8];
    const int* sk = (const int*)d_in[9];

    int I = in_sizes[3];  // rho
    int J = in_sizes[4];  // nu
    int K = in_sizes[5];  // tau
    int E = in_sizes[6];  // sample_weights

    init_kernel<<<(I + 255) / 256, 256>>>(I);

    int rows = I + J + K;
    norms_kernel<<<(rows * 32 + 255) / 256, 256>>>(L, R, U, I, J, K);

    dim3 g_rl(I / BI, J / BJ);
    exp_gemm_kernel<<<g_rl, 256>>>(R, L, nu, 0);
    dim3 g_ul(I / BI, K / BJ);
    exp_gemm_kernel<<<g_ul, 256>>>(U, L, tau, 1);

    edge_kernel<<<1184, 256>>>(L, R, U, rho, nu, tau, w, si, sj, sk, E);

    final_kernel<<<1, 256>>>(rho, I, (float*)d_out);
}

// round 9
// speedup vs baseline: 1.0016x; 1.0002x over previous
#include <cuda_runtime.h>

#define EPS 1e-6f
#define D_DIM 128
#define MAX_I 16384
#define MAX_JK 8192

// ---- scratch (no allocations allowed) ----
__device__ float  g_col_rl[MAX_I];
__device__ float  g_col_ul[MAX_I];
__device__ float  g_cL[MAX_I];      // |l_i|^2 - 2*eps*sum(l_i)
__device__ float  g_normR[MAX_JK];  // |r_j + eps|^2
__device__ float  g_normU[MAX_JK];  // |u_k + eps|^2
__device__ double g_edge;

__device__ __forceinline__ float fsqrt_approx(float x) {
    float r; asm("sqrt.approx.f32 %0, %1;" : "=f"(r) : "f"(x)); return r;
}
// packed fp32x2 FMA (Blackwell): c.lo += a.lo*b.lo ; c.hi += a.hi*b.hi
__device__ __forceinline__ void ffma2(unsigned long long &c,
                                      unsigned long long a,
                                      unsigned long long b) {
    asm("fma.rn.f32x2 %0, %1, %2, %0;" : "+l"(c) : "l"(a), "l"(b));
}

// ---------------------------------------------------------------- init
__global__ void init_kernel(int I) {
    int t = blockIdx.x * blockDim.x + threadIdx.x;
    if (t < I) { g_col_rl[t] = 0.f; g_col_ul[t] = 0.f; }
    if (t == 0) g_edge = 0.0;
}

// ------------------------------------------------------------- norms
// one warp per row; D=128 -> one float4 per lane
__global__ void norms_kernel(const float* __restrict__ L,
                             const float* __restrict__ R,
                             const float* __restrict__ U,
                             int I, int J, int K) {
    int warp = (blockIdx.x * blockDim.x + threadIdx.x) >> 5;
    int lane = threadIdx.x & 31;
    int rows = I + J + K;
    if (warp >= rows) return;

    const float* src; int mode, rowid;
    if (warp < J)          { src = R + (size_t)warp * D_DIM;          mode = 0; rowid = warp; }
    else if (warp < J + K) { src = U + (size_t)(warp - J) * D_DIM;    mode = 1; rowid = warp - J; }
    else                   { src = L + (size_t)(warp - J - K) * D_DIM; mode = 2; rowid = warp - J - K; }

    float4 v = ((const float4*)src)[lane];
    if (mode < 2) { v.x += EPS; v.y += EPS; v.z += EPS; v.w += EPS; }
    float s2 = v.x * v.x + v.y * v.y + v.z * v.z + v.w * v.w;
    float s1 = v.x + v.y + v.z + v.w;
    #pragma unroll
    for (int off = 16; off; off >>= 1) {
        s2 += __shfl_down_sync(0xffffffffu, s2, off);
        s1 += __shfl_down_sync(0xffffffffu, s1, off);
    }
    if (lane == 0) {
        if (mode == 0)      g_normR[rowid] = s2;
        else if (mode == 1) g_normU[rowid] = s2;
        else                g_cL[rowid]    = s2 - 2.0f * EPS * s1;
    }
}

// ----------------------------------------------------- fused exp-GEMM
// col[i] += sum_j exp(bias[j] - (sqrt(max(normA[j]+cL[i]-2*A_j.B_i,0)) + eps))
// Block tile: 128 (j) x 64 (i), 256 threads, per-thread 8x4, k paired in f32x2.
#define BJ 128
#define BI 64
#define BK 16
#define PITCH 18   // even (8B-aligned k-pairs), tx*18 mod 32 hits 16 distinct banks

__global__ __launch_bounds__(256, 2)
void exp_gemm_kernel(const float* __restrict__ A,   // [J, D]
                     const float* __restrict__ Bm,  // [I, D] (latent_l)
                     const float* __restrict__ bias,
                     int which)                     // 0: rl, 1: ul
{
    __shared__ float As[BJ * PITCH];
    __shared__ float Bs[BI * PITCH];
    __shared__ float cs[16][BI];

    const float* normA = which ? g_normU : g_normR;
    float* col         = which ? g_col_ul : g_col_rl;

    const int tid = threadIdx.x;
    const int tx = tid & 15, ty = tid >> 4;
    const int j0 = blockIdx.y * BJ;
    const int i0 = blockIdx.x * BI;

    unsigned long long acc[8][4];
    #pragma unroll
    for (int m = 0; m < 8; m++)
        #pragma unroll
        for (int n = 0; n < 4; n++) acc[m][n] = 0ull;

    for (int kk = 0; kk < D_DIM; kk += BK) {
        // stage A: 128 rows x 16 k = 512 float4 over 256 threads
        #pragma unroll
        for (int r2 = 0; r2 < 2; r2++) {
            int idx = tid + r2 * 256;
            int row = idx >> 2, c = idx & 3;
            float4 v = *(const float4*)(A + (size_t)(j0 + row) * D_DIM + kk + c * 4);
            float* s = &As[row * PITCH + c * 4];
            s[0] = v.x; s[1] = v.y; s[2] = v.z; s[3] = v.w;
        }
        // stage B: 64 rows x 16 k = 256 float4
        {
            int row = tid >> 2, c = tid & 3;
            float4 v = *(const float4*)(Bm + (size_t)(i0 + row) * D_DIM + kk + c * 4);
            float* s = &Bs[row * PITCH + c * 4];
            s[0] = v.x; s[1] = v.y; s[2] = v.z; s[3] = v.w;
        }
        __syncthreads();

        #pragma unroll
        for (int kp = 0; kp < 8; kp++) {
            unsigned long long a2[8], b2[4];
            #pragma unroll
            for (int m = 0; m < 8; m++)
                a2[m] = *(const unsigned long long*)&As[(ty + 16 * m) * PITCH + kp * 2];
            #pragma unroll
            for (int n = 0; n < 4; n++)
                b2[n] = *(const unsigned long long*)&Bs[(tx + 16 * n) * PITCH + kp * 2];
            #pragma unroll
            for (int m = 0; m < 8; m++)
                #pragma unroll
                for (int n = 0; n < 4; n++)
                    ffma2(acc[m][n], a2[m], b2[n]);
        }
        __syncthreads();
    }

    // epilogue: fold k-pair halves, distance -> exp -> column sums over j
    float na[8], ba[8];
    #pragma unroll
    for (int m = 0; m < 8; m++) {
        int j = j0 + ty + 16 * m;
        na[m] = normA[j];
        ba[m] = bias[j];
    }
    #pragma unroll
    for (int n = 0; n < 4; n++) {
        int il = tx + 16 * n;
        float cb = g_cL[i0 + il];
        float csum = 0.f;
        #pragma unroll
        for (int m = 0; m < 8; m++) {
            float lo, hi;
            asm("mov.b64 {%0,%1}, %2;" : "=f"(lo), "=f"(hi) : "l"(acc[m][n]));
            float dot = lo + hi;
            float d2  = na[m] + cb - 2.f * dot;
            float d   = fsqrt_approx(fmaxf(d2, 0.f)) + EPS;
            csum += __expf(ba[m] - d);
        }
        cs[ty][il] = csum;
    }
    __syncthreads();
    if (tid < BI) {
        float s = 0.f;
        #pragma unroll
        for (int t2 = 0; t2 < 16; t2++) s += cs[t2][tid];
        atomicAdd(&col[i0 + tid], s);
    }
}

// -------------------------------------------------------------- edges
// 8 lanes per edge, grid-stride; coalesced float4 row gathers (L2-resident tables)
__global__ void edge_kernel(const float* __restrict__ L, const float* __restrict__ R,
                            const float* __restrict__ U,
                            const float* __restrict__ rho, const float* __restrict__ nu,
                            const float* __restrict__ tau,
                            const float* __restrict__ w,
                            const int* __restrict__ si, const int* __restrict__ sj,
                            const int* __restrict__ sk, int E)
{
    const int lane8 = threadIdx.x & 7;
    int grp  = (blockIdx.x * blockDim.x + threadIdx.x) >> 3;
    int ngrp = (gridDim.x * blockDim.x) >> 3;

    float local = 0.f;
    for (int e = grp; e < E; e += ngrp) {
        int ii = si[e], jj = sj[e], kk = sk[e];
        const float4* lp = (const float4*)(L + (size_t)ii * D_DIM);
        const float4* rp = (const float4*)(R + (size_t)jj * D_DIM);
        const float4* up = (const float4*)(U + (size_t)kk * D_DIM);
        float slr = 0.f, slu = 0.f;
        #pragma unroll
        for (int q = 0; q < 4; q++) {
            float4 lv = lp[q * 8 + lane8];
            float4 rv = rp[q * 8 + lane8];
            float4 uv = up[q * 8 + lane8];
            float d0 = lv.x - rv.x + EPS, d1 = lv.y - rv.y + EPS;
            float d2 = lv.z - rv.z + EPS, d3 = lv.w - rv.w + EPS;
            slr += d0 * d0 + d1 * d1 + d2 * d2 + d3 * d3;
            d0 = lv.x - uv.x + EPS; d1 = lv.y - uv.y + EPS;
            d2 = lv.z - uv.z + EPS; d3 = lv.w - uv.w + EPS;
            slu += d0 * d0 + d1 * d1 + d2 * d2 + d3 * d3;
        }
        #pragma unroll
        for (int off = 4; off; off >>= 1) {
            slr += __shfl_down_sync(0xffffffffu, slr, off, 8);
            slu += __shfl_down_sync(0xffffffffu, slu, off, 8);
        }
        if (lane8 == 0) {
            float bias = rho[ii] + nu[jj] + tau[kk];
            local += w[e] * (bias - fsqrt_approx(slr) - fsqrt_approx(slu));
        }
    }

    __shared__ float red[256];
    red[threadIdx.x] = local;
    __syncthreads();
    #pragma unroll
    for (int s = 128; s; s >>= 1) {
        if ((int)threadIdx.x < s) red[threadIdx.x] += red[threadIdx.x + s];
        __syncthreads();
    }
    if (threadIdx.x == 0) atomicAdd(&g_edge, (double)red[0]);
}

// -------------------------------------------------------------- final
__global__ void final_kernel(const float* __restrict__ rho, int I, float* __restrict__ out) {
    __shared__ double sd[256];
    double z1 = 0.0;
    for (int i = threadIdx.x; i < I; i += blockDim.x)
        z1 += (double)g_col_rl[i] * (double)g_col_ul[i] * (double)__expf(rho[i]);
    sd[threadIdx.x] = z1;
    __syncthreads();
    #pragma unroll
    for (int s = 128; s; s >>= 1) {
        if ((int)threadIdx.x < s) sd[threadIdx.x] += sd[threadIdx.x + s];
        __syncthreads();
    }
    if (threadIdx.x == 0) out[0] = (float)(g_edge - sd[0]);
}

// -------------------------------------------------------------- launch
extern "C" void kernel_launch(void* const* d_in, const int* in_sizes, int n_in,
                              void* d_out, int out_size) {
    const float* L   = (const float*)d_in[0];
    const float* R   = (const float*)d_in[1];
    const float* U   = (const float*)d_in[2];
    const float* rho = (const float*)d_in[3];
    const float* nu  = (const float*)d_in[4];
    const float* tau = (const float*)d_in[5];
    const float* w   = (const float*)d_in[6];
    const int* si = (const int*)d_in[7];
    const int* sj = (const int*)d_in[8];
    const int* sk = (const int*)d_in[9];

    int I = in_sizes[3];  // rho
    int J = in_sizes[4];  // nu
    int K = in_sizes[5];  // tau
    int E = in_sizes[6];  // sample_weights

    init_kernel<<<(I + 255) / 256, 256>>>(I);

    int rows = I + J + K;
    norms_kernel<<<(rows * 32 + 255) / 256, 256>>>(L, R, U, I, J, K);

    dim3 g_rl(I / BI, J / BJ);
    exp_gemm_kernel<<<g_rl, 256>>>(R, L, nu, 0);
    dim3 g_ul(I / BI, K / BJ);
    exp_gemm_kernel<<<g_ul, 256>>>(U, L, tau, 1);

    edge_kernel<<<1184, 256>>>(L, R, U, rho, nu, tau, w, si, sj, sk, E);

    final_kernel<<<1, 256>>>(rho, I, (float*)d_out);
}